// round 16
// baseline (speedup 1.0000x reference)
#include <cuda_runtime.h>
#include <cuda_bf16.h>
#include <cuda_fp16.h>
#include <math.h>
#include <stdint.h>

// ---------------- problem constants ----------------
#define B_   2
#define S_   4096
#define D_   512
#define BPL_ 4
#define H_   16
#define DQK_ 64
#define DLAT_ 1024
#define LQ_  (S_ / BPL_)          // 1024
#define EPS_ 1.1920929e-07f

// ---------------- scratch (device globals; no allocation allowed) ----------------
__device__ __half g_nh    [B_ * S_ * D_];
__device__ __half g_wqh   [BPL_ * D_ * H_ * DQK_];
__device__ __half g_wkvh  [D_ * 2 * H_ * DQK_];
__device__ __half g_qh    [B_ * H_ * LQ_ * DQK_];         // pre-scaled by 0.125
__device__ __half g_kh    [B_ * H_ * S_ * DQK_];
__device__ __half g_vh    [B_ * H_ * S_ * DQK_];
__device__ __half g_x16   [B_ * S_ * D_];
__device__ __half g_attn16[B_ * LQ_ * H_ * DQK_];
__device__ __half g_wout16[H_ * DQK_ * DLAT_];
__device__ __half g_wbyp16[BPL_ * D_ * DLAT_];

// ---------------- helpers ----------------
__device__ __forceinline__ uint32_t smem_to_u32(const void* p) {
    uint32_t a;
    asm("{ .reg .u64 t; cvta.to.shared.u64 t, %1; cvt.u32.u64 %0, t; }" : "=r"(a) : "l"(p));
    return a;
}

#define CP_ASYNC16(dst, src) \
    asm volatile("cp.async.cg.shared.global [%0], [%1], 16;" :: "r"(dst), "l"(src))
#define CP_COMMIT()  asm volatile("cp.async.commit_group;" ::: "memory")
#define CP_WAIT0()   asm volatile("cp.async.wait_group 0;" ::: "memory")
#define CP_WAIT1()   asm volatile("cp.async.wait_group 1;" ::: "memory")
#define CP_WAIT2()   asm volatile("cp.async.wait_group 2;" ::: "memory")

__device__ __forceinline__ void ldmA(uint32_t* r, uint32_t addr) {
    asm volatile("ldmatrix.sync.aligned.m8n8.x4.shared.b16 {%0,%1,%2,%3}, [%4];"
                 : "=r"(r[0]), "=r"(r[1]), "=r"(r[2]), "=r"(r[3]) : "r"(addr));
}
__device__ __forceinline__ void ldmBT(uint32_t* r, uint32_t addr) {
    asm volatile("ldmatrix.sync.aligned.m8n8.x4.trans.shared.b16 {%0,%1,%2,%3}, [%4];"
                 : "=r"(r[0]), "=r"(r[1]), "=r"(r[2]), "=r"(r[3]) : "r"(addr));
}
__device__ __forceinline__ void mma16816h(float* d, const uint32_t* a, uint32_t b0, uint32_t b1) {
    asm volatile(
        "mma.sync.aligned.m16n8k16.row.col.f32.f16.f16.f32 "
        "{%0,%1,%2,%3}, {%4,%5,%6,%7}, {%8,%9}, {%0,%1,%2,%3};"
        : "+f"(d[0]), "+f"(d[1]), "+f"(d[2]), "+f"(d[3])
        : "r"(a[0]), "r"(a[1]), "r"(a[2]), "r"(a[3]), "r"(b0), "r"(b1));
}

__device__ __forceinline__ uint32_t packhf(float x, float y) {
    union { __half2 h; uint32_t u; } c;
    c.h = __halves2half2(__float2half(x), __float2half(y));
    return c.u;
}

__device__ __forceinline__ uint2 conv4h(float4 v) {
    union { __half2 h[2]; uint2 u; } c;
    c.h[0] = __halves2half2(__float2half(v.x), __float2half(v.y));
    c.h[1] = __halves2half2(__float2half(v.z), __float2half(v.w));
    return c.u;
}

__device__ __forceinline__ float inv_freq_f(int d)
{
    return (float)pow(10000.0, -(double)d / 32.0);
}

// ---------------- elementwise kernels ----------------
#define WQ4   (BPL_ * D_ * H_ * DQK_ / 4)
#define WKV4  (D_ * 2 * H_ * DQK_ / 4)
#define WOUT4 (H_ * DQK_ * DLAT_ / 4)
#define WBYP4 (BPL_ * D_ * DLAT_ / 4)
#define WTOT4 (WQ4 + WKV4 + WOUT4 + WBYP4)

__global__ __launch_bounds__(256) void convw_kernel(
    const float* __restrict__ wq, const float* __restrict__ wkv,
    const float* __restrict__ wout, const float* __restrict__ wbyp,
    __half* __restrict__ wqh, __half* __restrict__ wkvh,
    __half* __restrict__ wouth, __half* __restrict__ wbyph)
{
    int i = blockIdx.x * blockDim.x + threadIdx.x;
    if (i >= WTOT4) return;
    const float* src;
    __half* dst;
    int j = i;
    if (j < WQ4)                       { src = wq;   dst = wqh; }
    else if ((j -= WQ4) < WKV4)        { src = wkv;  dst = wkvh; }
    else if ((j -= WKV4) < WOUT4)      { src = wout; dst = wouth; }
    else { j -= WOUT4;                   src = wbyp; dst = wbyph; }
    ((uint2*)dst)[j] = conv4h(((const float4*)src)[j]);
}

__global__ __launch_bounds__(128) void rmsnorm_kernel(
    const float* __restrict__ x, const float* __restrict__ w,
    __half* __restrict__ outh, __half* __restrict__ xh)
{
    int row = blockIdx.x;
    const float4* xr = (const float4*)(x + (size_t)row * D_);
    const float4* wr = (const float4*)w;
    int tid = threadIdx.x;

    float4 v = xr[tid];
    ((uint2*)xh)[row * (D_ / 4) + tid] = conv4h(v);

    float s = v.x * v.x + v.y * v.y + v.z * v.z + v.w * v.w;
    #pragma unroll
    for (int o = 16; o > 0; o >>= 1) s += __shfl_xor_sync(0xffffffffu, s, o);
    __shared__ float red[4];
    int warp = tid >> 5, lane = tid & 31;
    if (lane == 0) red[warp] = s;
    __syncthreads();
    float total = red[0] + red[1] + red[2] + red[3];
    float inv = rsqrtf(total / (float)D_ + EPS_);
    float4 wv = wr[tid];
    float4 o4 = make_float4(v.x * inv * wv.x, v.y * inv * wv.y,
                            v.z * inv * wv.z, v.w * inv * wv.w);
    ((uint2*)outh)[row * (D_ / 4) + tid] = conv4h(o4);
}

// ---------------- shared GEMM mainloop: 4-stage ring, one sync/chunk ----------------
#define BKF  32
#define ASTR 40
#define BSTR 136
#define G1_A_B (128 * ASTR * 2)            // 10240
#define G1_B_B (BKF * BSTR * 2)            // 8704
#define G1_STG (G1_A_B + G1_B_B)           // 18944
#define GSTAGES 4
#define G1_SMEM (GSTAGES * G1_STG)         // 75776

__device__ __forceinline__ void gemm_mainloop(
    uint32_t sBase, int N, int K,
    const __half* __restrict__ A, const __half* __restrict__ Bm,
    const float* __restrict__ bias,
    int mBase, int nBase, int warpM, int warpN, int tid, int lane,
    float acc[2][8][4])
{
    const int cpk = K / BKF;
    const int arow0 = tid >> 2, aseg = (tid & 3) * 8;
    const int brow0 = tid >> 4, bseg = (tid & 15) * 8;

    #pragma unroll
    for (int mi = 0; mi < 2; mi++)
        #pragma unroll
        for (int ni = 0; ni < 8; ni++)
            #pragma unroll
            for (int c = 0; c < 4; c++) acc[mi][ni][c] = 0.0f;

    auto issue = [&](int chunk) {
        int buf = chunk & (GSTAGES - 1);
        int k0 = chunk * BKF;
        uint32_t da = sBase + buf * G1_STG;
        uint32_t db = da + G1_A_B;
        const __half* aptr = A  + (size_t)mBase * K + k0 + aseg;
        const __half* bptr = Bm + (size_t)k0 * N + nBase + bseg;
        #pragma unroll
        for (int it = 0; it < 2; it++) {
            int row = arow0 + it * 64;
            CP_ASYNC16(da + row * (ASTR * 2) + aseg * 2, aptr + (size_t)row * K);
        }
        #pragma unroll
        for (int it = 0; it < 2; it++) {
            int row = brow0 + it * 16;
            CP_ASYNC16(db + row * (BSTR * 2) + bseg * 2, bptr + (size_t)row * N);
        }
        CP_COMMIT();
    };

    issue(0); issue(1); issue(2);

    for (int i = 0; i < cpk; i++) {
        // ensure chunk i's group has completed (≤ #newer-committed outstanding)
        if (i + 2 < cpk)      CP_WAIT2();
        else if (i + 1 < cpk) CP_WAIT1();
        else                  CP_WAIT0();
        __syncthreads();          // fences iter i-1 readers of buf (i-1)&3
        if (i + 3 < cpk) issue(i + 3);   // writes buf (i-1)&3 — safe after sync

        const uint32_t aBase = sBase + (i & (GSTAGES - 1)) * G1_STG;
        const uint32_t bBase = aBase + G1_A_B;

        #pragma unroll
        for (int kk = 0; kk < 2; kk++) {
            uint32_t afrag[2][4];
            #pragma unroll
            for (int mi = 0; mi < 2; mi++) {
                uint32_t addr = aBase
                    + (warpM + mi * 16 + (lane & 15)) * (ASTR * 2)
                    + ((lane >> 4) << 4) + kk * 32;
                ldmA(afrag[mi], addr);
            }
            uint32_t bf[4][4];
            int grp = lane >> 3, r = lane & 7;
            #pragma unroll
            for (int p = 0; p < 4; p++) {
                uint32_t addr = bBase
                    + (kk * 16 + (grp & 1) * 8 + r) * (BSTR * 2)
                    + (warpN + p * 16 + (grp >> 1) * 8) * 2;
                ldmBT(bf[p], addr);
            }
            #pragma unroll
            for (int mi = 0; mi < 2; mi++)
                #pragma unroll
                for (int ni = 0; ni < 8; ni++) {
                    int g = ni >> 1, s = (ni & 1) * 2;
                    mma16816h(acc[mi][ni], afrag[mi], bf[g][s], bf[g][s + 1]);
                }
        }
    }

    if (bias) {
        #pragma unroll
        for (int ni = 0; ni < 8; ni++) {
            int c = nBase + warpN + ni * 8 + (lane & 3) * 2;
            float2 bb = *(const float2*)(bias + c);
            #pragma unroll
            for (int mi = 0; mi < 2; mi++) {
                acc[mi][ni][0] += bb.x; acc[mi][ni][1] += bb.y;
                acc[mi][ni][2] += bb.x; acc[mi][ni][3] += bb.y;
            }
        }
    }
}

// ---------------- Q projection GEMM with fused RoPE epilogue ----------------
__global__ __launch_bounds__(256) void gemm_qproj(
    const __half* __restrict__ A, const __half* __restrict__ Bm,
    const float* __restrict__ bias, __half* __restrict__ qh)
{
    extern __shared__ char gsm[];
    const uint32_t sBase = smem_to_u32(gsm);
    const int tid = threadIdx.x;
    const int wid = tid >> 5, lane = tid & 31;
    const int mBase = blockIdx.y * 128;
    const int nBase = blockIdx.x * 128;
    const int warpM = (wid >> 1) * 32;
    const int warpN = (wid & 1) * 64;
    const int N = H_ * DQK_, K = BPL_ * D_;

    float acc[2][8][4];
    gemm_mainloop(sBase, N, K, A, Bm, bias, mBase, nBase, warpM, warpN, tid, lane, acc);

    const int hcol = (nBase + warpN) >> 6;

    #pragma unroll
    for (int mi = 0; mi < 2; mi++) {
        int r0 = mBase + warpM + mi * 16 + (lane >> 2);
        int r1 = r0 + 8;
        int qi0 = r0 & (LQ_ - 1), b0 = r0 >> 10;
        int qi1 = r1 & (LQ_ - 1), b1 = r1 >> 10;
        float pos0 = (float)(qi0 * BPL_), pos1 = (float)(qi1 * BPL_);
        size_t base0 = (((size_t)(b0 * H_ + hcol) * LQ_) + qi0) * DQK_;
        size_t base1 = (((size_t)(b1 * H_ + hcol) * LQ_) + qi1) * DQK_;
        #pragma unroll
        for (int ni = 0; ni < 4; ni++) {
            int d0 = ni * 8 + (lane & 3) * 2;
            float f0 = inv_freq_f(d0), f1 = inv_freq_f(d0 + 1);
            {
                float a0 = pos0 * f0, a1 = pos0 * f1;
                float c0 = cosf(a0), s0 = sinf(a0), c1 = cosf(a1), s1 = sinf(a1);
                float x1a = acc[mi][ni][0],     x1b = acc[mi][ni][1];
                float x2a = acc[mi][ni + 4][0], x2b = acc[mi][ni + 4][1];
                *(uint32_t*)(qh + base0 + d0) =
                    packhf((x1a * c0 - x2a * s0) * 0.125f, (x1b * c1 - x2b * s1) * 0.125f);
                *(uint32_t*)(qh + base0 + d0 + 32) =
                    packhf((x1a * s0 + x2a * c0) * 0.125f, (x1b * s1 + x2b * c1) * 0.125f);
            }
            {
                float a0 = pos1 * f0, a1 = pos1 * f1;
                float c0 = cosf(a0), s0 = sinf(a0), c1 = cosf(a1), s1 = sinf(a1);
                float x1a = acc[mi][ni][2],     x1b = acc[mi][ni][3];
                float x2a = acc[mi][ni + 4][2], x2b = acc[mi][ni + 4][3];
                *(uint32_t*)(qh + base1 + d0) =
                    packhf((x1a * c0 - x2a * s0) * 0.125f, (x1b * c1 - x2b * s1) * 0.125f);
                *(uint32_t*)(qh + base1 + d0 + 32) =
                    packhf((x1a * s0 + x2a * c0) * 0.125f, (x1b * s1 + x2b * c1) * 0.125f);
            }
        }
    }
}

// ---------------- KV projection GEMM with fused RoPE-K / transpose-V epilogue ----------------
__global__ __launch_bounds__(256) void gemm_kvproj(
    const __half* __restrict__ A, const __half* __restrict__ Bm,
    const float* __restrict__ bias,
    __half* __restrict__ kh, __half* __restrict__ vh)
{
    extern __shared__ char gsm[];
    const uint32_t sBase = smem_to_u32(gsm);
    const int tid = threadIdx.x;
    const int wid = tid >> 5, lane = tid & 31;
    const int mBase = blockIdx.y * 128;
    const int nBase = blockIdx.x * 128;
    const int warpM = (wid >> 1) * 32;
    const int warpN = (wid & 1) * 64;
    const int N = 2 * H_ * DQK_, K = D_;

    float acc[2][8][4];
    gemm_mainloop(sBase, N, K, A, Bm, bias, mBase, nBase, warpM, warpN, tid, lane, acc);

    const int colBase = nBase + warpN;
    const bool isK = colBase < H_ * DQK_;
    const int hcol = (colBase & (H_ * DQK_ - 1)) >> 6;

    #pragma unroll
    for (int mi = 0; mi < 2; mi++) {
        int r0 = mBase + warpM + mi * 16 + (lane >> 2);
        int r1 = r0 + 8;
        int s0 = r0 & (S_ - 1), b0 = r0 >> 12;
        int s1 = r1 & (S_ - 1), b1 = r1 >> 12;
        size_t base0 = (((size_t)(b0 * H_ + hcol) * S_) + s0) * DQK_;
        size_t base1 = (((size_t)(b1 * H_ + hcol) * S_) + s1) * DQK_;

        if (isK) {
            float pos0 = (float)s0, pos1 = (float)s1;
            #pragma unroll
            for (int ni = 0; ni < 4; ni++) {
                int d0 = ni * 8 + (lane & 3) * 2;
                float f0 = inv_freq_f(d0), f1 = inv_freq_f(d0 + 1);
                {
                    float a0 = pos0 * f0, a1 = pos0 * f1;
                    float c0 = cosf(a0), sn0 = sinf(a0), c1 = cosf(a1), sn1 = sinf(a1);
                    float x1a = acc[mi][ni][0],     x1b = acc[mi][ni][1];
                    float x2a = acc[mi][ni + 4][0], x2b = acc[mi][ni + 4][1];
                    *(uint32_t*)(kh + base0 + d0) =
                        packhf(x1a * c0 - x2a * sn0, x1b * c1 - x2b * sn1);
                    *(uint32_t*)(kh + base0 + d0 + 32) =
                        packhf(x1a * sn0 + x2a * c0, x1b * sn1 + x2b * c1);
                }
                {
                    float a0 = pos1 * f0, a1 = pos1 * f1;
                    float c0 = cosf(a0), sn0 = sinf(a0), c1 = cosf(a1), sn1 = sinf(a1);
                    float x1a = acc[mi][ni][2],     x1b = acc[mi][ni][3];
                    float x2a = acc[mi][ni + 4][2], x2b = acc[mi][ni + 4][3];
                    *(uint32_t*)(kh + base1 + d0) =
                        packhf(x1a * c0 - x2a * sn0, x1b * c1 - x2b * sn1);
                    *(uint32_t*)(kh + base1 + d0 + 32) =
                        packhf(x1a * sn0 + x2a * c0, x1b * sn1 + x2b * c1);
                }
            }
        } else {
            #pragma unroll
            for (int ni = 0; ni < 8; ni++) {
                int d0 = ni * 8 + (lane & 3) * 2;
                *(uint32_t*)(vh + base0 + d0) = packhf(acc[mi][ni][0], acc[mi][ni][1]);
                *(uint32_t*)(vh + base1 + d0) = packhf(acc[mi][ni][2], acc[mi][ni][3]);
            }
        }
    }
}

// ---------------- fused final GEMM: out = x16@wbyp + attn16@wout + wout_b ----------------
__global__ __launch_bounds__(256) void gemm_final(
    const __half* __restrict__ Ax,   // x16 [2048, 2048]
    const __half* __restrict__ Aat,  // attn16 [2048, 1024]
    const __half* __restrict__ Bbyp, // [2048, 1024]
    const __half* __restrict__ Bout, // [1024, 1024]
    const float* __restrict__ bias, float* __restrict__ C)
{
    extern __shared__ char gsm[];
    const uint32_t sBase = smem_to_u32(gsm);
    const int tid = threadIdx.x;
    const int wid = tid >> 5, lane = tid & 31;
    const int mBase = blockIdx.y * 128;
    const int nBase = blockIdx.x * 128;
    const int warpM = (wid >> 1) * 32;
    const int warpN = (wid & 1) * 64;

    const int N  = DLAT_;
    const int KA = BPL_ * D_;       // 2048 (segment boundary, chunk-aligned)
    const int KT = KA + H_ * DQK_;  // 3072
    const int cpk = KT / BKF;       // 96

    const int arow0 = tid >> 2, aseg = (tid & 3) * 8;
    const int brow0 = tid >> 4, bseg = (tid & 15) * 8;

    float acc[2][8][4];
    #pragma unroll
    for (int mi = 0; mi < 2; mi++)
        #pragma unroll
        for (int ni = 0; ni < 8; ni++)
            #pragma unroll
            for (int c = 0; c < 4; c++) acc[mi][ni][c] = 0.0f;

    auto issue = [&](int chunk) {
        int buf = chunk & (GSTAGES - 1);
        int k0 = chunk * BKF;
        uint32_t da = sBase + buf * G1_STG;
        uint32_t db = da + G1_A_B;
        const __half* aptr;
        size_t astr;
        const __half* bptr;
        if (k0 < KA) {
            aptr = Ax + (size_t)mBase * KA + k0 + aseg;
            astr = KA;
            bptr = Bbyp + (size_t)k0 * N + nBase + bseg;
        } else {
            int k1 = k0 - KA;
            aptr = Aat + (size_t)mBase * (H_ * DQK_) + k1 + aseg;
            astr = H_ * DQK_;
            bptr = Bout + (size_t)k1 * N + nBase + bseg;
        }
        #pragma unroll
        for (int it = 0; it < 2; it++) {
            int row = arow0 + it * 64;
            CP_ASYNC16(da + row * (ASTR * 2) + aseg * 2, aptr + (size_t)row * astr);
        }
        #pragma unroll
        for (int it = 0; it < 2; it++) {
            int row = brow0 + it * 16;
            CP_ASYNC16(db + row * (BSTR * 2) + bseg * 2, bptr + (size_t)row * N);
        }
        CP_COMMIT();
    };

    issue(0); issue(1); issue(2);

    for (int i = 0; i < cpk; i++) {
        if (i + 2 < cpk)      CP_WAIT2();
        else if (i + 1 < cpk) CP_WAIT1();
        else                  CP_WAIT0();
        __syncthreads();
        if (i + 3 < cpk) issue(i + 3);

        const uint32_t aBase = sBase + (i & (GSTAGES - 1)) * G1_STG;
        const uint32_t bBase = aBase + G1_A_B;

        #pragma unroll
        for (int kk = 0; kk < 2; kk++) {
            uint32_t afrag[2][4];
            #pragma unroll
            for (int mi = 0; mi < 2; mi++) {
                uint32_t addr = aBase
                    + (warpM + mi * 16 + (lane & 15)) * (ASTR * 2)
                    + ((lane >> 4) << 4) + kk * 32;
                ldmA(afrag[mi], addr);
            }
            uint32_t bf[4][4];
            int grp = lane >> 3, r = lane & 7;
            #pragma unroll
            for (int p = 0; p < 4; p++) {
                uint32_t addr = bBase
                    + (kk * 16 + (grp & 1) * 8 + r) * (BSTR * 2)
                    + (warpN + p * 16 + (grp >> 1) * 8) * 2;
                ldmBT(bf[p], addr);
            }
            #pragma unroll
            for (int mi = 0; mi < 2; mi++)
                #pragma unroll
                for (int ni = 0; ni < 8; ni++) {
                    int g = ni >> 1, s = (ni & 1) * 2;
                    mma16816h(acc[mi][ni], afrag[mi], bf[g][s], bf[g][s + 1]);
                }
        }
    }

    #pragma unroll
    for (int mi = 0; mi < 2; mi++) {
        #pragma unroll
        for (int ni = 0; ni < 8; ni++) {
            int r0 = mBase + warpM + mi * 16 + (lane >> 2);
            int c  = nBase + warpN + ni * 8 + (lane & 3) * 2;
            float2 bb = *(const float2*)(bias + c);
            float2 v0 = make_float2(acc[mi][ni][0] + bb.x, acc[mi][ni][1] + bb.y);
            float2 v1 = make_float2(acc[mi][ni][2] + bb.x, acc[mi][ni][3] + bb.y);
            *(float2*)(C + (size_t)r0 * N + c) = v0;
            *(float2*)(C + (size_t)(r0 + 8) * N + c) = v1;
        }
    }
}

// ---------------- flash attention via fp16 mma (single-term) ----------------
#define FSTG 18432
#define FSMEM (2 * FSTG)

__global__ __launch_bounds__(256, 2) void flash_mma(
    const __half* __restrict__ qh,
    const __half* __restrict__ kh, const __half* __restrict__ vh,
    __half* __restrict__ oh)
{
    extern __shared__ char sm[];
    const uint32_t sb = smem_to_u32(sm);
    const int tid = threadIdx.x, wid = tid >> 5, lane = tid & 31;
    const int bh = blockIdx.y;
    const int q0 = blockIdx.x * 128;
    const int warpM = wid * 16;
    const size_t qoff = ((size_t)bh * LQ_ + q0) * DQK_;
    const size_t koff = (size_t)bh * S_ * DQK_;

    {
        #pragma unroll
        for (int it = 0; it < 4; it++) {
            int e = it * 256 + tid;
            int row = e >> 3, seg = (e & 7) * 8;
            CP_ASYNC16(sb + FSTG + row * 144 + seg * 2, qh + qoff + (size_t)row * DQK_ + seg);
        }
        CP_COMMIT();
    }

    auto issueKV = [&](int tile, int stage) {
        int sk = tile * 64;
        uint32_t dst = sb + stage * FSTG;
        #pragma unroll
        for (int it = 0; it < 2; it++) {
            int e = it * 256 + tid;
            int row = e >> 3, seg = (e & 7) * 8;
            size_t g = koff + (size_t)(sk + row) * DQK_ + seg;
            uint32_t so = row * 144 + seg * 2;
            CP_ASYNC16(dst + so,        kh + g);
            CP_ASYNC16(dst + 9216 + so, vh + g);
        }
    };

    issueKV(0, 0); CP_COMMIT();
    CP_WAIT1(); __syncthreads();

    uint32_t Qf[4][4];
    #pragma unroll
    for (int kt = 0; kt < 4; kt++) {
        uint32_t ad = sb + FSTG + (warpM + (lane & 15)) * 144 + ((lane >> 4) << 4) + kt * 32;
        ldmA(Qf[kt], ad);
    }
    __syncthreads();
    issueKV(1, 1); CP_COMMIT();

    float acc[8][4];
    #pragma unroll
    for (int n = 0; n < 8; n++)
        #pragma unroll
        for (int c = 0; c < 4; c++) acc[n][c] = 0.0f;
    float m0 = -1e30f, m1 = -1e30f, l0 = 0.0f, l1 = 0.0f;

    for (int i = 0; i < S_ / 64; i++) {
        CP_WAIT1(); __syncthreads();
        const uint32_t kb = sb + (i & 1) * FSTG;

        float sc[8][4];
        #pragma unroll
        for (int n = 0; n < 8; n++)
            #pragma unroll
            for (int c = 0; c < 4; c++) sc[n][c] = 0.0f;

        #pragma unroll
        for (int kt = 0; kt < 4; kt++) {
            uint32_t Bh[4][4];
            #pragma unroll
            for (int p = 0; p < 4; p++) {
                uint32_t ad = kb + (p * 16 + (lane & 15)) * 144 + ((lane >> 4) << 4) + kt * 32;
                ldmA(Bh[p], ad);
            }
            #pragma unroll
            for (int ni = 0; ni < 8; ni++) {
                int g = ni >> 1, s = ni & 1;
                mma16816h(sc[ni], Qf[kt], Bh[g][s], Bh[g][s + 2]);
            }
        }

        float r0 = -1e30f, r1 = -1e30f;
        #pragma unroll
        for (int ni = 0; ni < 8; ni++) {
            r0 = fmaxf(r0, fmaxf(sc[ni][0], sc[ni][1]));
            r1 = fmaxf(r1, fmaxf(sc[ni][2], sc[ni][3]));
        }
        r0 = fmaxf(r0, __shfl_xor_sync(0xffffffffu, r0, 1));
        r0 = fmaxf(r0, __shfl_xor_sync(0xffffffffu, r0, 2));
        r1 = fmaxf(r1, __shfl_xor_sync(0xffffffffu, r1, 1));
        r1 = fmaxf(r1, __shfl_xor_sync(0xffffffffu, r1, 2));
        float mn0 = fmaxf(m0, r0), mn1 = fmaxf(m1, r1);
        float c0 = __expf(m0 - mn0), c1 = __expf(m1 - mn1);
        l0 *= c0; l1 *= c1;
        #pragma unroll
        for (int ni = 0; ni < 8; ni++) {
            acc[ni][0] *= c0; acc[ni][1] *= c0;
            acc[ni][2] *= c1; acc[ni][3] *= c1;
        }
        m0 = mn0; m1 = mn1;

        #pragma unroll
        for (int kt = 0; kt < 4; kt++) {
            uint32_t ph[4];
            #pragma unroll
            for (int j = 0; j < 2; j++) {
                int ni = 2 * kt + j;
                float p0 = __expf(sc[ni][0] - m0);
                float p1 = __expf(sc[ni][1] - m0);
                float p2 = __expf(sc[ni][2] - m1);
                float p3 = __expf(sc[ni][3] - m1);
                l0 += p0 + p1; l1 += p2 + p3;
                ph[2 * j]     = packhf(p0, p1);
                ph[2 * j + 1] = packhf(p2, p3);
            }
            uint32_t Vf[4][4];
            int grp = lane >> 3, rr = lane & 7;
            #pragma unroll
            for (int p = 0; p < 4; p++) {
                uint32_t ad = kb + 9216
                    + (kt * 16 + (grp & 1) * 8 + rr) * 144
                    + (p * 16 + (grp >> 1) * 8) * 2;
                ldmBT(Vf[p], ad);
            }
            #pragma unroll
            for (int nv = 0; nv < 8; nv++) {
                int g = nv >> 1, s = (nv & 1) * 2;
                mma16816h(acc[nv], ph, Vf[g][s], Vf[g][s + 1]);
            }
        }

        __syncthreads();
        if (i + 2 < S_ / 64) issueKV(i + 2, i & 1);
        CP_COMMIT();
    }

    l0 += __shfl_xor_sync(0xffffffffu, l0, 1);
    l0 += __shfl_xor_sync(0xffffffffu, l0, 2);
    l1 += __shfl_xor_sync(0xffffffffu, l1, 1);
    l1 += __shfl_xor_sync(0xffffffffu, l1, 2);
    float i0 = 1.0f / l0, i1 = 1.0f / l1;

    int b = bh >> 4, h = bh & 15;
    int row0 = q0 + warpM + (lane >> 2);
    size_t ob0 = (size_t)(b * LQ_ + row0) * (H_ * DQK_) + h * DQK_;
    size_t ob1 = ob0 + (size_t)8 * (H_ * DQK_);
    #pragma unroll
    for (int nv = 0; nv < 8; nv++) {
        int col = nv * 8 + (lane & 3) * 2;
        *(uint32_t*)(oh + ob0 + col) = packhf(acc[nv][0] * i0, acc[nv][1] * i0);
        *(uint32_t*)(oh + ob1 + col) = packhf(acc[nv][2] * i1, acc[nv][3] * i1);
    }
}

// ---------------- launch ----------------
extern "C" void kernel_launch(void* const* d_in, const int* in_sizes, int n_in,
                              void* d_out, int out_size)
{
    (void)in_sizes; (void)n_in; (void)out_size;
    const float* x      = (const float*)d_in[0];
    const float* norm_w = (const float*)d_in[1];
    const float* wq_w   = (const float*)d_in[2];
    const float* wq_b   = (const float*)d_in[3];
    const float* wkv_w  = (const float*)d_in[4];
    const float* wkv_b  = (const float*)d_in[5];
    const float* wout_w = (const float*)d_in[6];
    const float* wout_b = (const float*)d_in[7];
    const float* wbyp_w = (const float*)d_in[8];
    float* out = (float*)d_out;

    __half *nh, *wqh, *wkvh, *pqh, *pkh, *pvh, *x16, *at16, *wout16, *wbyp16;
    cudaGetSymbolAddress((void**)&nh,     g_nh);
    cudaGetSymbolAddress((void**)&wqh,    g_wqh);
    cudaGetSymbolAddress((void**)&wkvh,   g_wkvh);
    cudaGetSymbolAddress((void**)&pqh,    g_qh);
    cudaGetSymbolAddress((void**)&pkh,    g_kh);
    cudaGetSymbolAddress((void**)&pvh,    g_vh);
    cudaGetSymbolAddress((void**)&x16,    g_x16);
    cudaGetSymbolAddress((void**)&at16,   g_attn16);
    cudaGetSymbolAddress((void**)&wout16, g_wout16);
    cudaGetSymbolAddress((void**)&wbyp16, g_wbyp16);

    cudaFuncSetAttribute(flash_mma,   cudaFuncAttributeMaxDynamicSharedMemorySize, FSMEM);
    cudaFuncSetAttribute(gemm_qproj,  cudaFuncAttributeMaxDynamicSharedMemorySize, G1_SMEM);
    cudaFuncSetAttribute(gemm_kvproj, cudaFuncAttributeMaxDynamicSharedMemorySize, G1_SMEM);
    cudaFuncSetAttribute(gemm_final,  cudaFuncAttributeMaxDynamicSharedMemorySize, G1_SMEM);

    // 1. RMSNorm -> nh (fp16) + x16 (fp16)
    rmsnorm_kernel<<<B_ * S_, 128>>>(x, norm_w, nh, x16);

    // 2. all weight conversions in one launch
    convw_kernel<<<(WTOT4 + 255) / 256, 256>>>(
        wq_w, wkv_w, wout_w, wbyp_w, wqh, wkvh, wout16, wbyp16);

    // 3. Q projection + fused RoPE -> qh
    gemm_qproj<<<dim3((H_ * DQK_) / 128, (B_ * LQ_) / 128), 256, G1_SMEM>>>(
        nh, wqh, wq_b, pqh);

    // 4. KV projection + fused RoPE-K / transpose-V -> kh, vh
    gemm_kvproj<<<dim3((2 * H_ * DQK_) / 128, (B_ * S_) / 128), 256, G1_SMEM>>>(
        nh, wkvh, wkv_b, pkh, pvh);

    // 5. Flash attention -> attn fp16
    flash_mma<<<dim3(LQ_ / 128, B_ * H_), 256, FSMEM>>>(pqh, pkh, pvh, at16);

    // 6. Fused final GEMM: out = x16@wbyp + attn16@wout + wout_b
    gemm_final<<<dim3(DLAT_ / 128, (B_ * LQ_) / 128), 256, G1_SMEM>>>(
        x16, at16, wbyp16, wout16, wout_b, out);
}

// round 17
// speedup vs baseline: 1.0115x; 1.0115x over previous
#include <cuda_runtime.h>
#include <cuda_bf16.h>
#include <cuda_fp16.h>
#include <math.h>
#include <stdint.h>

// ---------------- problem constants ----------------
#define B_   2
#define S_   4096
#define D_   512
#define BPL_ 4
#define H_   16
#define DQK_ 64
#define DLAT_ 1024
#define LQ_  (S_ / BPL_)          // 1024
#define EPS_ 1.1920929e-07f

// ---------------- scratch (device globals; no allocation allowed) ----------------
__device__ __half g_nh    [B_ * S_ * D_];
__device__ __half g_wqh   [BPL_ * D_ * H_ * DQK_];
__device__ __half g_wkvh  [D_ * 2 * H_ * DQK_];
__device__ __half g_qh    [B_ * H_ * LQ_ * DQK_];         // pre-scaled by 0.125
__device__ __half g_kh    [B_ * H_ * S_ * DQK_];
__device__ __half g_vh    [B_ * H_ * S_ * DQK_];
__device__ __half g_x16   [B_ * S_ * D_];
__device__ __half g_attn16[B_ * LQ_ * H_ * DQK_];
__device__ __half g_wout16[H_ * DQK_ * DLAT_];
__device__ __half g_wbyp16[BPL_ * D_ * DLAT_];

// ---------------- helpers ----------------
__device__ __forceinline__ uint32_t smem_to_u32(const void* p) {
    uint32_t a;
    asm("{ .reg .u64 t; cvta.to.shared.u64 t, %1; cvt.u32.u64 %0, t; }" : "=r"(a) : "l"(p));
    return a;
}

#define CP_ASYNC16(dst, src) \
    asm volatile("cp.async.cg.shared.global [%0], [%1], 16;" :: "r"(dst), "l"(src))
#define CP_COMMIT()  asm volatile("cp.async.commit_group;" ::: "memory")
#define CP_WAIT0()   asm volatile("cp.async.wait_group 0;" ::: "memory")
#define CP_WAIT1()   asm volatile("cp.async.wait_group 1;" ::: "memory")

__device__ __forceinline__ void ldmA(uint32_t* r, uint32_t addr) {
    asm volatile("ldmatrix.sync.aligned.m8n8.x4.shared.b16 {%0,%1,%2,%3}, [%4];"
                 : "=r"(r[0]), "=r"(r[1]), "=r"(r[2]), "=r"(r[3]) : "r"(addr));
}
__device__ __forceinline__ void ldmBT(uint32_t* r, uint32_t addr) {
    asm volatile("ldmatrix.sync.aligned.m8n8.x4.trans.shared.b16 {%0,%1,%2,%3}, [%4];"
                 : "=r"(r[0]), "=r"(r[1]), "=r"(r[2]), "=r"(r[3]) : "r"(addr));
}
__device__ __forceinline__ void mma16816h(float* d, const uint32_t* a, uint32_t b0, uint32_t b1) {
    asm volatile(
        "mma.sync.aligned.m16n8k16.row.col.f32.f16.f16.f32 "
        "{%0,%1,%2,%3}, {%4,%5,%6,%7}, {%8,%9}, {%0,%1,%2,%3};"
        : "+f"(d[0]), "+f"(d[1]), "+f"(d[2]), "+f"(d[3])
        : "r"(a[0]), "r"(a[1]), "r"(a[2]), "r"(a[3]), "r"(b0), "r"(b1));
}

__device__ __forceinline__ uint32_t packhf(float x, float y) {
    union { __half2 h; uint32_t u; } c;
    c.h = __halves2half2(__float2half(x), __float2half(y));
    return c.u;
}

__device__ __forceinline__ uint2 conv4h(float4 v) {
    union { __half2 h[2]; uint2 u; } c;
    c.h[0] = __halves2half2(__float2half(v.x), __float2half(v.y));
    c.h[1] = __halves2half2(__float2half(v.z), __float2half(v.w));
    return c.u;
}

__device__ __forceinline__ float inv_freq_f(int d)
{
    return (float)pow(10000.0, -(double)d / 32.0);
}

// ---------------- elementwise kernels ----------------
#define WQ4   (BPL_ * D_ * H_ * DQK_ / 4)
#define WKV4  (D_ * 2 * H_ * DQK_ / 4)
#define WOUT4 (H_ * DQK_ * DLAT_ / 4)
#define WBYP4 (BPL_ * D_ * DLAT_ / 4)
#define WTOT4 (WQ4 + WKV4 + WOUT4 + WBYP4)

__global__ __launch_bounds__(256) void convw_kernel(
    const float* __restrict__ wq, const float* __restrict__ wkv,
    const float* __restrict__ wout, const float* __restrict__ wbyp,
    __half* __restrict__ wqh, __half* __restrict__ wkvh,
    __half* __restrict__ wouth, __half* __restrict__ wbyph)
{
    int i = blockIdx.x * blockDim.x + threadIdx.x;
    if (i >= WTOT4) return;
    const float* src;
    __half* dst;
    int j = i;
    if (j < WQ4)                       { src = wq;   dst = wqh; }
    else if ((j -= WQ4) < WKV4)        { src = wkv;  dst = wkvh; }
    else if ((j -= WKV4) < WOUT4)      { src = wout; dst = wouth; }
    else { j -= WOUT4;                   src = wbyp; dst = wbyph; }
    ((uint2*)dst)[j] = conv4h(((const float4*)src)[j]);
}

__global__ __launch_bounds__(128) void rmsnorm_kernel(
    const float* __restrict__ x, const float* __restrict__ w,
    __half* __restrict__ outh, __half* __restrict__ xh)
{
    int row = blockIdx.x;
    const float4* xr = (const float4*)(x + (size_t)row * D_);
    const float4* wr = (const float4*)w;
    int tid = threadIdx.x;

    float4 v = xr[tid];
    ((uint2*)xh)[row * (D_ / 4) + tid] = conv4h(v);

    float s = v.x * v.x + v.y * v.y + v.z * v.z + v.w * v.w;
    #pragma unroll
    for (int o = 16; o > 0; o >>= 1) s += __shfl_xor_sync(0xffffffffu, s, o);
    __shared__ float red[4];
    int warp = tid >> 5, lane = tid & 31;
    if (lane == 0) red[warp] = s;
    __syncthreads();
    float total = red[0] + red[1] + red[2] + red[3];
    float inv = rsqrtf(total / (float)D_ + EPS_);
    float4 wv = wr[tid];
    float4 o4 = make_float4(v.x * inv * wv.x, v.y * inv * wv.y,
                            v.z * inv * wv.z, v.w * inv * wv.w);
    ((uint2*)outh)[row * (D_ / 4) + tid] = conv4h(o4);
}

// ---------------- shared GEMM mainloop (2-stage, R15-winning version) ----------------
#define BKF  32
#define ASTR 40
#define BSTR 136
#define G1_A_B (128 * ASTR * 2)            // 10240
#define G1_B_B (BKF * BSTR * 2)            // 8704
#define G1_STG (G1_A_B + G1_B_B)           // 18944
#define G1_SMEM (2 * G1_STG)               // 37888

__device__ __forceinline__ void gemm_mainloop(
    uint32_t sBase, int N, int K,
    const __half* __restrict__ A, const __half* __restrict__ Bm,
    const float* __restrict__ bias,
    int mBase, int nBase, int warpM, int warpN, int tid, int lane,
    float acc[2][8][4])
{
    const int cpk = K / BKF;
    const int arow0 = tid >> 2, aseg = (tid & 3) * 8;
    const int brow0 = tid >> 4, bseg = (tid & 15) * 8;

    #pragma unroll
    for (int mi = 0; mi < 2; mi++)
        #pragma unroll
        for (int ni = 0; ni < 8; ni++)
            #pragma unroll
            for (int c = 0; c < 4; c++) acc[mi][ni][c] = 0.0f;

    auto issue = [&](int chunk) {
        int buf = chunk & 1;
        int k0 = chunk * BKF;
        uint32_t da = sBase + buf * G1_STG;
        uint32_t db = da + G1_A_B;
        const __half* aptr = A  + (size_t)mBase * K + k0 + aseg;
        const __half* bptr = Bm + (size_t)k0 * N + nBase + bseg;
        #pragma unroll
        for (int it = 0; it < 2; it++) {
            int row = arow0 + it * 64;
            CP_ASYNC16(da + row * (ASTR * 2) + aseg * 2, aptr + (size_t)row * K);
        }
        #pragma unroll
        for (int it = 0; it < 2; it++) {
            int row = brow0 + it * 16;
            CP_ASYNC16(db + row * (BSTR * 2) + bseg * 2, bptr + (size_t)row * N);
        }
        CP_COMMIT();
    };

    issue(0);

    for (int i = 0; i < cpk; i++) {
        if (i + 1 < cpk) { issue(i + 1); CP_WAIT1(); }
        else             { CP_WAIT0(); }
        __syncthreads();

        const uint32_t aBase = sBase + (i & 1) * G1_STG;
        const uint32_t bBase = aBase + G1_A_B;

        #pragma unroll
        for (int kk = 0; kk < 2; kk++) {
            uint32_t afrag[2][4];
            #pragma unroll
            for (int mi = 0; mi < 2; mi++) {
                uint32_t addr = aBase
                    + (warpM + mi * 16 + (lane & 15)) * (ASTR * 2)
                    + ((lane >> 4) << 4) + kk * 32;
                ldmA(afrag[mi], addr);
            }
            uint32_t bf[4][4];
            int grp = lane >> 3, r = lane & 7;
            #pragma unroll
            for (int p = 0; p < 4; p++) {
                uint32_t addr = bBase
                    + (kk * 16 + (grp & 1) * 8 + r) * (BSTR * 2)
                    + (warpN + p * 16 + (grp >> 1) * 8) * 2;
                ldmBT(bf[p], addr);
            }
            #pragma unroll
            for (int mi = 0; mi < 2; mi++)
                #pragma unroll
                for (int ni = 0; ni < 8; ni++) {
                    int g = ni >> 1, s = (ni & 1) * 2;
                    mma16816h(acc[mi][ni], afrag[mi], bf[g][s], bf[g][s + 1]);
                }
        }
        __syncthreads();
    }

    if (bias) {
        #pragma unroll
        for (int ni = 0; ni < 8; ni++) {
            int c = nBase + warpN + ni * 8 + (lane & 3) * 2;
            float2 bb = *(const float2*)(bias + c);
            #pragma unroll
            for (int mi = 0; mi < 2; mi++) {
                acc[mi][ni][0] += bb.x; acc[mi][ni][1] += bb.y;
                acc[mi][ni][2] += bb.x; acc[mi][ni][3] += bb.y;
            }
        }
    }
}

// ---------------- merged Q + KV projection kernel ----------------
// CTAs [0, 1024): kvproj (long pole, scheduled first).
// CTAs [1024, 1152): qproj (backfills kvproj's tail wave).
#define KV_CTAS 1024

__global__ __launch_bounds__(256) void gemm_qkv(
    const __half* __restrict__ A,
    const __half* __restrict__ Wq, const __half* __restrict__ Wkv,
    const float* __restrict__ qb, const float* __restrict__ kvb,
    __half* __restrict__ qh, __half* __restrict__ kh, __half* __restrict__ vh)
{
    extern __shared__ char gsm[];
    const uint32_t sBase = smem_to_u32(gsm);
    const int tid = threadIdx.x;
    const int wid = tid >> 5, lane = tid & 31;
    const int warpM = (wid >> 1) * 32;
    const int warpN = (wid & 1) * 64;
    const int cid = blockIdx.x;

    float acc[2][8][4];

    if (cid < KV_CTAS) {
        // ---- KV projection: M=8192, N=2048, K=512 ----
        const int nBase = (cid & 15) * 128;
        const int mBase = (cid >> 4) * 128;
        const int N = 2 * H_ * DQK_, K = D_;

        gemm_mainloop(sBase, N, K, A, Wkv, kvb, mBase, nBase, warpM, warpN, tid, lane, acc);

        const int colBase = nBase + warpN;
        const bool isK = colBase < H_ * DQK_;
        const int hcol = (colBase & (H_ * DQK_ - 1)) >> 6;

        #pragma unroll
        for (int mi = 0; mi < 2; mi++) {
            int r0 = mBase + warpM + mi * 16 + (lane >> 2);
            int r1 = r0 + 8;
            int s0 = r0 & (S_ - 1), b0 = r0 >> 12;
            int s1 = r1 & (S_ - 1), b1 = r1 >> 12;
            size_t base0 = (((size_t)(b0 * H_ + hcol) * S_) + s0) * DQK_;
            size_t base1 = (((size_t)(b1 * H_ + hcol) * S_) + s1) * DQK_;

            if (isK) {
                float pos0 = (float)s0, pos1 = (float)s1;
                #pragma unroll
                for (int ni = 0; ni < 4; ni++) {
                    int d0 = ni * 8 + (lane & 3) * 2;
                    float f0 = inv_freq_f(d0), f1 = inv_freq_f(d0 + 1);
                    {
                        float a0 = pos0 * f0, a1 = pos0 * f1;
                        float c0 = cosf(a0), sn0 = sinf(a0), c1 = cosf(a1), sn1 = sinf(a1);
                        float x1a = acc[mi][ni][0],     x1b = acc[mi][ni][1];
                        float x2a = acc[mi][ni + 4][0], x2b = acc[mi][ni + 4][1];
                        *(uint32_t*)(kh + base0 + d0) =
                            packhf(x1a * c0 - x2a * sn0, x1b * c1 - x2b * sn1);
                        *(uint32_t*)(kh + base0 + d0 + 32) =
                            packhf(x1a * sn0 + x2a * c0, x1b * sn1 + x2b * c1);
                    }
                    {
                        float a0 = pos1 * f0, a1 = pos1 * f1;
                        float c0 = cosf(a0), sn0 = sinf(a0), c1 = cosf(a1), sn1 = sinf(a1);
                        float x1a = acc[mi][ni][2],     x1b = acc[mi][ni][3];
                        float x2a = acc[mi][ni + 4][2], x2b = acc[mi][ni + 4][3];
                        *(uint32_t*)(kh + base1 + d0) =
                            packhf(x1a * c0 - x2a * sn0, x1b * c1 - x2b * sn1);
                        *(uint32_t*)(kh + base1 + d0 + 32) =
                            packhf(x1a * sn0 + x2a * c0, x1b * sn1 + x2b * c1);
                    }
                }
            } else {
                #pragma unroll
                for (int ni = 0; ni < 8; ni++) {
                    int d0 = ni * 8 + (lane & 3) * 2;
                    *(uint32_t*)(vh + base0 + d0) = packhf(acc[mi][ni][0], acc[mi][ni][1]);
                    *(uint32_t*)(vh + base1 + d0) = packhf(acc[mi][ni][2], acc[mi][ni][3]);
                }
            }
        }
    } else {
        // ---- Q projection: M=2048, N=1024, K=2048 ----
        const int c = cid - KV_CTAS;
        const int nBase = (c & 7) * 128;
        const int mBase = (c >> 3) * 128;
        const int N = H_ * DQK_, K = BPL_ * D_;

        gemm_mainloop(sBase, N, K, A, Wq, qb, mBase, nBase, warpM, warpN, tid, lane, acc);

        const int hcol = (nBase + warpN) >> 6;

        #pragma unroll
        for (int mi = 0; mi < 2; mi++) {
            int r0 = mBase + warpM + mi * 16 + (lane >> 2);
            int r1 = r0 + 8;
            int qi0 = r0 & (LQ_ - 1), b0 = r0 >> 10;
            int qi1 = r1 & (LQ_ - 1), b1 = r1 >> 10;
            float pos0 = (float)(qi0 * BPL_), pos1 = (float)(qi1 * BPL_);
            size_t base0 = (((size_t)(b0 * H_ + hcol) * LQ_) + qi0) * DQK_;
            size_t base1 = (((size_t)(b1 * H_ + hcol) * LQ_) + qi1) * DQK_;
            #pragma unroll
            for (int ni = 0; ni < 4; ni++) {
                int d0 = ni * 8 + (lane & 3) * 2;
                float f0 = inv_freq_f(d0), f1 = inv_freq_f(d0 + 1);
                {
                    float a0 = pos0 * f0, a1 = pos0 * f1;
                    float c0 = cosf(a0), s0 = sinf(a0), c1 = cosf(a1), s1 = sinf(a1);
                    float x1a = acc[mi][ni][0],     x1b = acc[mi][ni][1];
                    float x2a = acc[mi][ni + 4][0], x2b = acc[mi][ni + 4][1];
                    *(uint32_t*)(qh + base0 + d0) =
                        packhf((x1a * c0 - x2a * s0) * 0.125f, (x1b * c1 - x2b * s1) * 0.125f);
                    *(uint32_t*)(qh + base0 + d0 + 32) =
                        packhf((x1a * s0 + x2a * c0) * 0.125f, (x1b * s1 + x2b * c1) * 0.125f);
                }
                {
                    float a0 = pos1 * f0, a1 = pos1 * f1;
                    float c0 = cosf(a0), s0 = sinf(a0), c1 = cosf(a1), s1 = sinf(a1);
                    float x1a = acc[mi][ni][2],     x1b = acc[mi][ni][3];
                    float x2a = acc[mi][ni + 4][2], x2b = acc[mi][ni + 4][3];
                    *(uint32_t*)(qh + base1 + d0) =
                        packhf((x1a * c0 - x2a * s0) * 0.125f, (x1b * c1 - x2b * s1) * 0.125f);
                    *(uint32_t*)(qh + base1 + d0 + 32) =
                        packhf((x1a * s0 + x2a * c0) * 0.125f, (x1b * s1 + x2b * c1) * 0.125f);
                }
            }
        }
    }
}

// ---------------- fused final GEMM: out = x16@wbyp + attn16@wout + wout_b ----------------
__global__ __launch_bounds__(256) void gemm_final(
    const __half* __restrict__ Ax,   // x16 [2048, 2048]
    const __half* __restrict__ Aat,  // attn16 [2048, 1024]
    const __half* __restrict__ Bbyp, // [2048, 1024]
    const __half* __restrict__ Bout, // [1024, 1024]
    const float* __restrict__ bias, float* __restrict__ C)
{
    extern __shared__ char gsm[];
    const uint32_t sBase = smem_to_u32(gsm);
    const int tid = threadIdx.x;
    const int wid = tid >> 5, lane = tid & 31;
    const int mBase = blockIdx.y * 128;
    const int nBase = blockIdx.x * 128;
    const int warpM = (wid >> 1) * 32;
    const int warpN = (wid & 1) * 64;

    const int N  = DLAT_;
    const int KA = BPL_ * D_;       // 2048 (segment boundary, chunk-aligned)
    const int KT = KA + H_ * DQK_;  // 3072
    const int cpk = KT / BKF;       // 96

    const int arow0 = tid >> 2, aseg = (tid & 3) * 8;
    const int brow0 = tid >> 4, bseg = (tid & 15) * 8;

    float acc[2][8][4];
    #pragma unroll
    for (int mi = 0; mi < 2; mi++)
        #pragma unroll
        for (int ni = 0; ni < 8; ni++)
            #pragma unroll
            for (int c = 0; c < 4; c++) acc[mi][ni][c] = 0.0f;

    auto issue = [&](int chunk) {
        int buf = chunk & 1;
        int k0 = chunk * BKF;
        uint32_t da = sBase + buf * G1_STG;
        uint32_t db = da + G1_A_B;
        const __half* aptr;
        size_t astr;
        const __half* bptr;
        if (k0 < KA) {
            aptr = Ax + (size_t)mBase * KA + k0 + aseg;
            astr = KA;
            bptr = Bbyp + (size_t)k0 * N + nBase + bseg;
        } else {
            int k1 = k0 - KA;
            aptr = Aat + (size_t)mBase * (H_ * DQK_) + k1 + aseg;
            astr = H_ * DQK_;
            bptr = Bout + (size_t)k1 * N + nBase + bseg;
        }
        #pragma unroll
        for (int it = 0; it < 2; it++) {
            int row = arow0 + it * 64;
            CP_ASYNC16(da + row * (ASTR * 2) + aseg * 2, aptr + (size_t)row * astr);
        }
        #pragma unroll
        for (int it = 0; it < 2; it++) {
            int row = brow0 + it * 16;
            CP_ASYNC16(db + row * (BSTR * 2) + bseg * 2, bptr + (size_t)row * N);
        }
        CP_COMMIT();
    };

    issue(0);

    for (int i = 0; i < cpk; i++) {
        if (i + 1 < cpk) { issue(i + 1); CP_WAIT1(); }
        else             { CP_WAIT0(); }
        __syncthreads();

        const uint32_t aBase = sBase + (i & 1) * G1_STG;
        const uint32_t bBase = aBase + G1_A_B;

        #pragma unroll
        for (int kk = 0; kk < 2; kk++) {
            uint32_t afrag[2][4];
            #pragma unroll
            for (int mi = 0; mi < 2; mi++) {
                uint32_t addr = aBase
                    + (warpM + mi * 16 + (lane & 15)) * (ASTR * 2)
                    + ((lane >> 4) << 4) + kk * 32;
                ldmA(afrag[mi], addr);
            }
            uint32_t bf[4][4];
            int grp = lane >> 3, r = lane & 7;
            #pragma unroll
            for (int p = 0; p < 4; p++) {
                uint32_t addr = bBase
                    + (kk * 16 + (grp & 1) * 8 + r) * (BSTR * 2)
                    + (warpN + p * 16 + (grp >> 1) * 8) * 2;
                ldmBT(bf[p], addr);
            }
            #pragma unroll
            for (int mi = 0; mi < 2; mi++)
                #pragma unroll
                for (int ni = 0; ni < 8; ni++) {
                    int g = ni >> 1, s = (ni & 1) * 2;
                    mma16816h(acc[mi][ni], afrag[mi], bf[g][s], bf[g][s + 1]);
                }
        }
        __syncthreads();
    }

    #pragma unroll
    for (int mi = 0; mi < 2; mi++) {
        #pragma unroll
        for (int ni = 0; ni < 8; ni++) {
            int r0 = mBase + warpM + mi * 16 + (lane >> 2);
            int c  = nBase + warpN + ni * 8 + (lane & 3) * 2;
            float2 bb = *(const float2*)(bias + c);
            float2 v0 = make_float2(acc[mi][ni][0] + bb.x, acc[mi][ni][1] + bb.y);
            float2 v1 = make_float2(acc[mi][ni][2] + bb.x, acc[mi][ni][3] + bb.y);
            *(float2*)(C + (size_t)r0 * N + c) = v0;
            *(float2*)(C + (size_t)(r0 + 8) * N + c) = v1;
        }
    }
}

// ---------------- flash attention via fp16 mma (single-term) ----------------
#define FSTG 18432
#define FSMEM (2 * FSTG)

__global__ __launch_bounds__(256, 2) void flash_mma(
    const __half* __restrict__ qh,
    const __half* __restrict__ kh, const __half* __restrict__ vh,
    __half* __restrict__ oh)
{
    extern __shared__ char sm[];
    const uint32_t sb = smem_to_u32(sm);
    const int tid = threadIdx.x, wid = tid >> 5, lane = tid & 31;
    const int bh = blockIdx.y;
    const int q0 = blockIdx.x * 128;
    const int warpM = wid * 16;
    const size_t qoff = ((size_t)bh * LQ_ + q0) * DQK_;
    const size_t koff = (size_t)bh * S_ * DQK_;

    {
        #pragma unroll
        for (int it = 0; it < 4; it++) {
            int e = it * 256 + tid;
            int row = e >> 3, seg = (e & 7) * 8;
            CP_ASYNC16(sb + FSTG + row * 144 + seg * 2, qh + qoff + (size_t)row * DQK_ + seg);
        }
        CP_COMMIT();
    }

    auto issueKV = [&](int tile, int stage) {
        int sk = tile * 64;
        uint32_t dst = sb + stage * FSTG;
        #pragma unroll
        for (int it = 0; it < 2; it++) {
            int e = it * 256 + tid;
            int row = e >> 3, seg = (e & 7) * 8;
            size_t g = koff + (size_t)(sk + row) * DQK_ + seg;
            uint32_t so = row * 144 + seg * 2;
            CP_ASYNC16(dst + so,        kh + g);
            CP_ASYNC16(dst + 9216 + so, vh + g);
        }
    };

    issueKV(0, 0); CP_COMMIT();
    CP_WAIT1(); __syncthreads();

    uint32_t Qf[4][4];
    #pragma unroll
    for (int kt = 0; kt < 4; kt++) {
        uint32_t ad = sb + FSTG + (warpM + (lane & 15)) * 144 + ((lane >> 4) << 4) + kt * 32;
        ldmA(Qf[kt], ad);
    }
    __syncthreads();
    issueKV(1, 1); CP_COMMIT();

    float acc[8][4];
    #pragma unroll
    for (int n = 0; n < 8; n++)
        #pragma unroll
        for (int c = 0; c < 4; c++) acc[n][c] = 0.0f;
    float m0 = -1e30f, m1 = -1e30f, l0 = 0.0f, l1 = 0.0f;

    for (int i = 0; i < S_ / 64; i++) {
        CP_WAIT1(); __syncthreads();
        const uint32_t kb = sb + (i & 1) * FSTG;

        float sc[8][4];
        #pragma unroll
        for (int n = 0; n < 8; n++)
            #pragma unroll
            for (int c = 0; c < 4; c++) sc[n][c] = 0.0f;

        #pragma unroll
        for (int kt = 0; kt < 4; kt++) {
            uint32_t Bh[4][4];
            #pragma unroll
            for (int p = 0; p < 4; p++) {
                uint32_t ad = kb + (p * 16 + (lane & 15)) * 144 + ((lane >> 4) << 4) + kt * 32;
                ldmA(Bh[p], ad);
            }
            #pragma unroll
            for (int ni = 0; ni < 8; ni++) {
                int g = ni >> 1, s = ni & 1;
                mma16816h(sc[ni], Qf[kt], Bh[g][s], Bh[g][s + 2]);
            }
        }

        float r0 = -1e30f, r1 = -1e30f;
        #pragma unroll
        for (int ni = 0; ni < 8; ni++) {
            r0 = fmaxf(r0, fmaxf(sc[ni][0], sc[ni][1]));
            r1 = fmaxf(r1, fmaxf(sc[ni][2], sc[ni][3]));
        }
        r0 = fmaxf(r0, __shfl_xor_sync(0xffffffffu, r0, 1));
        r0 = fmaxf(r0, __shfl_xor_sync(0xffffffffu, r0, 2));
        r1 = fmaxf(r1, __shfl_xor_sync(0xffffffffu, r1, 1));
        r1 = fmaxf(r1, __shfl_xor_sync(0xffffffffu, r1, 2));
        float mn0 = fmaxf(m0, r0), mn1 = fmaxf(m1, r1);
        float c0 = __expf(m0 - mn0), c1 = __expf(m1 - mn1);
        l0 *= c0; l1 *= c1;
        #pragma unroll
        for (int ni = 0; ni < 8; ni++) {
            acc[ni][0] *= c0; acc[ni][1] *= c0;
            acc[ni][2] *= c1; acc[ni][3] *= c1;
        }
        m0 = mn0; m1 = mn1;

        #pragma unroll
        for (int kt = 0; kt < 4; kt++) {
            uint32_t ph[4];
            #pragma unroll
            for (int j = 0; j < 2; j++) {
                int ni = 2 * kt + j;
                float p0 = __expf(sc[ni][0] - m0);
                float p1 = __expf(sc[ni][1] - m0);
                float p2 = __expf(sc[ni][2] - m1);
                float p3 = __expf(sc[ni][3] - m1);
                l0 += p0 + p1; l1 += p2 + p3;
                ph[2 * j]     = packhf(p0, p1);
                ph[2 * j + 1] = packhf(p2, p3);
            }
            uint32_t Vf[4][4];
            int grp = lane >> 3, rr = lane & 7;
            #pragma unroll
            for (int p = 0; p < 4; p++) {
                uint32_t ad = kb + 9216
                    + (kt * 16 + (grp & 1) * 8 + rr) * 144
                    + (p * 16 + (grp >> 1) * 8) * 2;
                ldmBT(Vf[p], ad);
            }
            #pragma unroll
            for (int nv = 0; nv < 8; nv++) {
                int g = nv >> 1, s = (nv & 1) * 2;
                mma16816h(acc[nv], ph, Vf[g][s], Vf[g][s + 1]);
            }
        }

        __syncthreads();
        if (i + 2 < S_ / 64) issueKV(i + 2, i & 1);
        CP_COMMIT();
    }

    l0 += __shfl_xor_sync(0xffffffffu, l0, 1);
    l0 += __shfl_xor_sync(0xffffffffu, l0, 2);
    l1 += __shfl_xor_sync(0xffffffffu, l1, 1);
    l1 += __shfl_xor_sync(0xffffffffu, l1, 2);
    float i0 = 1.0f / l0, i1 = 1.0f / l1;

    int b = bh >> 4, h = bh & 15;
    int row0 = q0 + warpM + (lane >> 2);
    size_t ob0 = (size_t)(b * LQ_ + row0) * (H_ * DQK_) + h * DQK_;
    size_t ob1 = ob0 + (size_t)8 * (H_ * DQK_);
    #pragma unroll
    for (int nv = 0; nv < 8; nv++) {
        int col = nv * 8 + (lane & 3) * 2;
        *(uint32_t*)(oh + ob0 + col) = packhf(acc[nv][0] * i0, acc[nv][1] * i0);
        *(uint32_t*)(oh + ob1 + col) = packhf(acc[nv][2] * i1, acc[nv][3] * i1);
    }
}

// ---------------- launch ----------------
extern "C" void kernel_launch(void* const* d_in, const int* in_sizes, int n_in,
                              void* d_out, int out_size)
{
    (void)in_sizes; (void)n_in; (void)out_size;
    const float* x      = (const float*)d_in[0];
    const float* norm_w = (const float*)d_in[1];
    const float* wq_w   = (const float*)d_in[2];
    const float* wq_b   = (const float*)d_in[3];
    const float* wkv_w  = (const float*)d_in[4];
    const float* wkv_b  = (const float*)d_in[5];
    const float* wout_w = (const float*)d_in[6];
    const float* wout_b = (const float*)d_in[7];
    const float* wbyp_w = (const float*)d_in[8];
    float* out = (float*)d_out;

    __half *nh, *wqh, *wkvh, *pqh, *pkh, *pvh, *x16, *at16, *wout16, *wbyp16;
    cudaGetSymbolAddress((void**)&nh,     g_nh);
    cudaGetSymbolAddress((void**)&wqh,    g_wqh);
    cudaGetSymbolAddress((void**)&wkvh,   g_wkvh);
    cudaGetSymbolAddress((void**)&pqh,    g_qh);
    cudaGetSymbolAddress((void**)&pkh,    g_kh);
    cudaGetSymbolAddress((void**)&pvh,    g_vh);
    cudaGetSymbolAddress((void**)&x16,    g_x16);
    cudaGetSymbolAddress((void**)&at16,   g_attn16);
    cudaGetSymbolAddress((void**)&wout16, g_wout16);
    cudaGetSymbolAddress((void**)&wbyp16, g_wbyp16);

    cudaFuncSetAttribute(flash_mma,  cudaFuncAttributeMaxDynamicSharedMemorySize, FSMEM);
    cudaFuncSetAttribute(gemm_qkv,   cudaFuncAttributeMaxDynamicSharedMemorySize, G1_SMEM);
    cudaFuncSetAttribute(gemm_final, cudaFuncAttributeMaxDynamicSharedMemorySize, G1_SMEM);

    // 1. RMSNorm -> nh (fp16) + x16 (fp16)
    rmsnorm_kernel<<<B_ * S_, 128>>>(x, norm_w, nh, x16);

    // 2. all weight conversions in one launch
    convw_kernel<<<(WTOT4 + 255) / 256, 256>>>(
        wq_w, wkv_w, wout_w, wbyp_w, wqh, wkvh, wout16, wbyp16);

    // 3. Merged Q + KV projections (kvproj CTAs first, qproj backfills tail)
    gemm_qkv<<<KV_CTAS + 128, 256, G1_SMEM>>>(
        nh, wqh, wkvh, wq_b, wkv_b, pqh, pkh, pvh);

    // 4. Flash attention -> attn fp16
    flash_mma<<<dim3(LQ_ / 128, B_ * H_), 256, FSMEM>>>(pqh, pkh, pvh, at16);

    // 5. Fused final GEMM: out = x16@wbyp + attn16@wout + wout_b
    gemm_final<<<dim3(DLAT_ / 128, (B_ * LQ_) / 128), 256, G1_SMEM>>>(
        x16, at16, wbyp16, wout16, wout_b, out);
}